// round 8
// baseline (speedup 1.0000x reference)
#include <cuda_runtime.h>
#include <math.h>

// ---------------------------------------------------------------------------
// SimpleConvGRU on GB300 — round 5:
//  * recurrent convs: 4 rows x 8 px per warp, NC=1, weights in registers
//    (9 LDG per 288 FFMA2), full-column tiles, blend = single wave.
//  * setup fused into 2 kernels so ncu -s5 -c1 lands on conv_gh_zrh_k.
// ---------------------------------------------------------------------------

typedef unsigned long long ull;

#define B_ 16
#define T_ 28
#define NIMG_ 448            // B*T
#define PP_ 1156             // 34*34 padded pixels

// ---------------- device scratch (zero-initialized at load) ----------------
__device__ float g_Xpad[(size_t)NIMG_ * PP_ * 24];
__device__ float g_XG[(size_t)2 * NIMG_ * 1024 * 192];   // unpadded gates
__device__ float g_Y0[(size_t)NIMG_ * PP_ * 128];        // padded
__device__ float g_Y1[(size_t)NIMG_ * PP_ * 128];        // padded
__device__ float g_RH[(size_t)32 * PP_ * 64];            // padded
__device__ float g_Z [(size_t)32 * 1024 * 64];           // unpadded
__device__ float g_XC[(size_t)NIMG_ * PP_ * 256];        // padded
__device__ float g_WT[1041408];                          // transposed weights

// transposed-weight offsets (floats)
#define OFF_XF0   0
#define OFF_XB0   41472
#define OFF_ZRF0  82944
#define OFF_ZRB0  156672
#define OFF_HF0   230400
#define OFF_HB0   267264
#define OFF_XF1   304128
#define OFF_XB1   525312
#define OFF_ZRF1  746496
#define OFF_ZRB1  820224
#define OFF_HF1   893952
#define OFF_HB1   930816
#define OFF_C1    967680

// ---------------- packed f32x2 helpers ----------------
__device__ __forceinline__ void fma2(ull& d, ull a, ull b) {
    asm("fma.rn.f32x2 %0, %1, %2, %0;" : "+l"(d) : "l"(a), "l"(b));
}
__device__ __forceinline__ float red2(ull a) {
    float lo, hi;
    asm("mov.b64 {%0,%1}, %2;" : "=f"(lo), "=f"(hi) : "l"(a));
    return lo + hi;
}
__device__ __forceinline__ float sigm(float x) { return 1.0f / (1.0f + expf(-x)); }

// ---------------------------------------------------------------------------
// Stage 10-row tile (for 8-px-per-thread batch kernels).
// ---------------------------------------------------------------------------
template<int CINH, int CSTRIDE>
__device__ __forceinline__ void stage_tile(const float* __restrict__ gBase, ull* s)
{
    constexpr int TOT = 100 * CINH;
#pragma unroll 4
    for (int i = threadIdx.x; i < TOT; i += 256) {
        int r   = i / (10 * CINH);
        int rem = i - r * (10 * CINH);
        int c   = rem / CINH;
        int cp  = rem - c * CINH;
        s[i] = *(const ull*)(gBase + (long)(r * 34 + c) * CSTRIDE + 2 * cp);
    }
}

// ---------------------------------------------------------------------------
// Stage full-column tile: 34 rows x 10 cols x CINH cin-pairs.
// ---------------------------------------------------------------------------
template<int CINH, int CSTRIDE>
__device__ __forceinline__ void stage_col(const float* __restrict__ gBase, ull* s)
{
    constexpr int TOT = 340 * CINH;
#pragma unroll 4
    for (int i = threadIdx.x; i < TOT; i += 256) {
        int r   = i / (10 * CINH);
        int rem = i - r * (10 * CINH);
        int c   = rem / CINH;
        int cp  = rem - c * CINH;
        s[i] = *(const ull*)(gBase + (long)(r * 34 + c) * CSTRIDE + 2 * cp);
    }
}

// ---------------------------------------------------------------------------
// 8-px conv core (batch kernels): one warp = 1 row x 8 px x NC*32 couts.
// ---------------------------------------------------------------------------
template<int CINH, int WCO, int NC>
__device__ __forceinline__ void conv_core_s(
    const ull* sW, const float* __restrict__ wt, int coutIdx, ull acc[NC][8])
{
#pragma unroll
    for (int nc = 0; nc < NC; nc++)
#pragma unroll
        for (int p = 0; p < 8; p++) acc[nc][p] = 0ull;

    const float* wP = wt + coutIdx * 2;

#pragma unroll 1
    for (int cp = 0; cp < CINH; cp++) {
#pragma unroll
        for (int ky = 0; ky < 3; ky++) {
            ull v[10];
#pragma unroll
            for (int q = 0; q < 10; q++)
                v[q] = sW[(ky * 10 + q) * CINH + cp];
#pragma unroll
            for (int kx = 0; kx < 3; kx++) {
#pragma unroll
                for (int nc = 0; nc < NC; nc++) {
                    ull w = *(const ull*)(wP + ((ky * 3 + kx) * CINH * WCO + nc * 32) * 2);
#pragma unroll
                    for (int p = 0; p < 8; p++)
                        fma2(acc[nc][p], v[p + kx], w);
                }
            }
        }
        wP += WCO * 2;
    }
}

// ---------------------------------------------------------------------------
// 4-row x 8-px conv core (recurrent kernels). Warp covers output rows
// 4*warp+1 .. 4*warp+4 (padded). Weights (9 taps) held in registers per cp:
// 288 FFMA2 per 9 LDG + 60 LDS.
// ---------------------------------------------------------------------------
template<int CINH, int WCO>
__device__ __forceinline__ void conv_core4(
    const ull* sT, int warp, const float* __restrict__ wt, int coutIdx,
    ull acc[4][8])
{
#pragma unroll
    for (int o = 0; o < 4; o++)
#pragma unroll
        for (int p = 0; p < 8; p++) acc[o][p] = 0ull;

    const ull* sW = sT + (4 * warp) * 10 * CINH;
    const float* wP = wt + coutIdx * 2;

#pragma unroll 1
    for (int cp = 0; cp < CINH; cp++) {
        ull w[9];
#pragma unroll
        for (int t = 0; t < 9; t++)
            w[t] = *(const ull*)(wP + (long)t * CINH * WCO * 2);
#pragma unroll
        for (int r = 0; r < 6; r++) {
            ull v[10];
#pragma unroll
            for (int q = 0; q < 10; q++)
                v[q] = sW[(r * 10 + q) * CINH + cp];
#pragma unroll
            for (int o = 0; o < 4; o++) {
                if (o <= r && r <= o + 2) {
                    int ky = r - o;
#pragma unroll
                    for (int kx = 0; kx < 3; kx++) {
#pragma unroll
                        for (int p = 0; p < 8; p++)
                            fma2(acc[o][p], v[p + kx], w[ky * 3 + kx]);
                    }
                }
            }
        }
        wP += WCO * 2;
    }
}

// ---------------------------------------------------------------------------
// Input-gate conv: (x or Y0, both dirs) -> XG (+bias). Cout=192 in 3 groups.
// ---------------------------------------------------------------------------
template<int CINH, int CSTRIDE>
__global__ __launch_bounds__(256, 2) void conv_gates_k(
    const float* __restrict__ in, long imgStride,
    const float* __restrict__ wtF, const float* __restrict__ wtB,
    const float* __restrict__ bF, const float* __restrict__ bB,
    float* __restrict__ XG)
{
    extern __shared__ ull sdyn[];
    int z = blockIdx.z;
    int dir = z / (NIMG_ * 3);
    int rem = z - dir * (NIMG_ * 3);
    int img = rem / 3, cg = rem - (rem / 3) * 3;
    int lane = threadIdx.x & 31, warp = threadIdx.x >> 5;
    int y  = blockIdx.y * 8 + warp + 1;
    int x0 = blockIdx.x * 8 + 1;
    int co = cg * 64 + lane;

    const float* inImg = in + (long)img * imgStride;
    stage_tile<CINH, CSTRIDE>(inImg + (long)((blockIdx.y * 8) * 34 + blockIdx.x * 8) * CSTRIDE, sdyn);
    __syncthreads();

    ull acc[2][8];
    conv_core_s<CINH, 192, 2>(sdyn + warp * 10 * CINH, dir ? wtB : wtF, co, acc);

    const float* bias = dir ? bB : bF;
    float* xg = XG + (((long)dir * NIMG_ + img) * 1024 + (long)(y - 1) * 32 + (x0 - 1)) * 192;
#pragma unroll
    for (int nc = 0; nc < 2; nc++) {
        int c = co + nc * 32;
        float bv = bias[c];
#pragma unroll
        for (int p = 0; p < 8; p++) xg[p * 192 + c] = red2(acc[nc][p]) + bv;
    }
}

// ---------------------------------------------------------------------------
// Recurrent gate conv (h_prev -> z or r) fused with sigmoid + RH = r*h.
// grid = (4, 1, 128): z = dir*64 + b*4 + cg. cg 0,1 = z gates; 2,3 = r gates.
// Block covers a full 32-row x 8-col column; warp = 4 rows.
// ---------------------------------------------------------------------------
__global__ __launch_bounds__(256, 2) void conv_gh_zrh_k(
    const float* __restrict__ Y,
    const float* __restrict__ wtF, const float* __restrict__ wtB,
    const float* __restrict__ XG, float* __restrict__ Z, float* __restrict__ RH,
    int tf, int tb)
{
    extern __shared__ ull sdyn[];
    int z = blockIdx.z;
    int dir = z >> 6, b = (z >> 2) & 15, cg = z & 3;
    int lane = threadIdx.x & 31, warp = threadIdx.x >> 5;
    int bx = blockIdx.x;
    int t = dir ? tb : tf;
    int tprev = dir ? tb + 1 : tf - 1;

    const float* hbase = Y + (long)(b * T_ + tprev) * PP_ * 128 + (dir ? 64 : 0);
    stage_col<32, 128>(hbase + (long)(bx * 8) * 128, sdyn);
    __syncthreads();

    ull acc[4][8];
    conv_core4<32, 128>(sdyn, warp, dir ? wtB : wtF, cg * 32 + lane, acc);

    int zr = cg >> 1;                 // 0 = z, 1 = r
    int c  = (cg & 1) * 32 + lane;
    const float* xg = XG + ((long)dir * NIMG_ + b * T_ + t) * 1024 * 192;
    if (zr == 0) {
        float* zp = Z + (long)(dir * 16 + b) * 1024 * 64;
#pragma unroll
        for (int o = 0; o < 4; o++) {
            int py = 4 * warp + o;        // unpadded row
#pragma unroll
            for (int p = 0; p < 8; p++) {
                int pix = py * 32 + bx * 8 + p;
                zp[(long)pix * 64 + c] = sigm(xg[(long)pix * 192 + c] + red2(acc[o][p]));
            }
        }
    } else {
        float* rh = RH + (long)(dir * 16 + b) * PP_ * 64;
#pragma unroll
        for (int o = 0; o < 4; o++) {
            int y = 4 * warp + 1 + o;     // padded row
#pragma unroll
            for (int p = 0; p < 8; p++) {
                int x = bx * 8 + 1 + p;   // padded col
                int pix = (y - 1) * 32 + (x - 1);
                float r = sigm(xg[(long)pix * 192 + 64 + c] + red2(acc[o][p]));
                float h = hbase[((long)y * 34 + x) * 128 + c];
                rh[((long)y * 34 + x) * 64 + c] = r * h;
            }
        }
    }
}

// ---------------------------------------------------------------------------
// Candidate conv (RH -> hh) fused with tanh + GRU blend, writes Y[t].
// grid = (4, 1, 64): z = dir*32 + b*2 + cg (cg = cout group of 32).
// ---------------------------------------------------------------------------
__global__ __launch_bounds__(256, 2) void conv_blend_k(
    const float* __restrict__ RH,
    const float* __restrict__ wtF, const float* __restrict__ wtB,
    const float* __restrict__ XG, const float* __restrict__ Z,
    float* __restrict__ Y, int tf, int tb)
{
    extern __shared__ ull sdyn[];
    int z = blockIdx.z;
    int dir = z >> 5, b = (z >> 1) & 15, cg = z & 1;
    int lane = threadIdx.x & 31, warp = threadIdx.x >> 5;
    int bx = blockIdx.x;
    int t = dir ? tb : tf;
    int tprev = dir ? tb + 1 : tf - 1;

    const float* in = RH + (long)(dir * 16 + b) * PP_ * 64;
    stage_col<32, 64>(in + (long)(bx * 8) * 64, sdyn);
    __syncthreads();

    ull acc[4][8];
    conv_core4<32, 64>(sdyn, warp, dir ? wtB : wtF, cg * 32 + lane, acc);

    int c = cg * 32 + lane;
    const float* xg = XG + ((long)dir * NIMG_ + b * T_ + t) * 1024 * 192;
    const float* zp = Z + (long)(dir * 16 + b) * 1024 * 64;
    const float* hprev = Y + (long)(b * T_ + tprev) * PP_ * 128 + (dir ? 64 : 0);
    float* yout = Y + (long)(b * T_ + t) * PP_ * 128 + (dir ? 64 : 0);
#pragma unroll
    for (int o = 0; o < 4; o++) {
        int y = 4 * warp + 1 + o;
#pragma unroll
        for (int p = 0; p < 8; p++) {
            int x = bx * 8 + 1 + p;
            int pix = (y - 1) * 32 + (x - 1);
            float cand = tanhf(xg[(long)pix * 192 + 128 + c] + red2(acc[o][p]));
            float zv = zp[(long)pix * 64 + c];
            float hv = hprev[((long)y * 34 + x) * 128 + c];
            yout[((long)y * 34 + x) * 128 + c] = zv * hv + (1.0f - zv) * cand;
        }
    }
}

// ---------------------------------------------------------------------------
// conv1 (256->32) fused with the 1x1 head + ReLU (warp-shuffle reduce).
// ---------------------------------------------------------------------------
__global__ __launch_bounds__(256, 2) void conv1_out_k(
    const float* __restrict__ XC, const float* __restrict__ wt,
    const float* __restrict__ bc, const float* __restrict__ wo,
    const float* __restrict__ bo, float* __restrict__ out)
{
    extern __shared__ ull sdyn[];
    int img = blockIdx.z;
    int lane = threadIdx.x & 31, warp = threadIdx.x >> 5;
    int y  = blockIdx.y * 8 + warp + 1;
    int x0 = blockIdx.x * 8 + 1;

    const float* inImg = XC + (long)img * PP_ * 256;
    stage_tile<128, 256>(inImg + (long)((blockIdx.y * 8) * 34 + blockIdx.x * 8) * 256, sdyn);
    __syncthreads();

    ull acc[1][8];
    conv_core_s<128, 32, 1>(sdyn + warp * 10 * 128, wt, lane, acc);

    float bv = bc[lane], wv = wo[lane], bov = bo[0];
    float* o = out + (long)img * 1024 + (long)(y - 1) * 32 + (x0 - 1);
#pragma unroll
    for (int p = 0; p < 8; p++) {
        float s = (red2(acc[0][p]) + bv) * wv;
        s += __shfl_xor_sync(0xffffffffu, s, 16);
        s += __shfl_xor_sync(0xffffffffu, s, 8);
        s += __shfl_xor_sync(0xffffffffu, s, 4);
        s += __shfl_xor_sync(0xffffffffu, s, 2);
        s += __shfl_xor_sync(0xffffffffu, s, 1);
        if (lane == 0) o[p] = fmaxf(s + bov, 0.0f);
    }
}

// ---------------------------------------------------------------------------
// t=0 step (h_prev = 0): y = (1-sig(xg_z)) * tanh(xg_h), elementwise.
// ---------------------------------------------------------------------------
__global__ __launch_bounds__(256) void zrh0_k(const float* __restrict__ XG,
                                              float* __restrict__ Y)
{
    int i = blockIdx.x * 256 + threadIdx.x;   // 2*16*1024*64
    int c = i & 63;
    int t1 = i >> 6;
    int pix = t1 & 1023;
    int t2 = t1 >> 10;
    int b = t2 & 15, dir = t2 >> 4;
    int t = dir ? T_ - 1 : 0;
    const float* xg = XG + (((long)dir * NIMG_ + b * T_ + t) * 1024 + pix) * 192;
    float zv = sigm(xg[c]);
    float yv = (1.0f - zv) * tanhf(xg[128 + c]);
    int yy = pix >> 5, xx = pix & 31;
    Y[((long)(b * T_ + t) * PP_ + (long)(yy + 1) * 34 + xx + 1) * 128 + dir * 64 + c] = yv;
}

// ---------------------------------------------------------------------------
// Fused setup kernels (single launch each so ncu -s5 hits the recurrence).
// ---------------------------------------------------------------------------
__global__ __launch_bounds__(256) void transpose_all_k(
    const float* __restrict__ wx_f0, const float* __restrict__ wh_f0,
    const float* __restrict__ wx_b0, const float* __restrict__ wh_b0,
    const float* __restrict__ wx_f1, const float* __restrict__ wh_f1,
    const float* __restrict__ wx_b1, const float* __restrict__ wh_b1,
    const float* __restrict__ w_conv1, float* __restrict__ WT)
{
    const float* src; long off; int CIN, COsrc, o0, WCO;
    switch (blockIdx.y) {
        case 0:  src = wx_f0;   off = OFF_XF0;  CIN = 24;  COsrc = 192; o0 = 0;   WCO = 192; break;
        case 1:  src = wx_b0;   off = OFF_XB0;  CIN = 24;  COsrc = 192; o0 = 0;   WCO = 192; break;
        case 2:  src = wh_f0;   off = OFF_ZRF0; CIN = 64;  COsrc = 192; o0 = 0;   WCO = 128; break;
        case 3:  src = wh_b0;   off = OFF_ZRB0; CIN = 64;  COsrc = 192; o0 = 0;   WCO = 128; break;
        case 4:  src = wh_f0;   off = OFF_HF0;  CIN = 64;  COsrc = 192; o0 = 128; WCO = 64;  break;
        case 5:  src = wh_b0;   off = OFF_HB0;  CIN = 64;  COsrc = 192; o0 = 128; WCO = 64;  break;
        case 6:  src = wx_f1;   off = OFF_XF1;  CIN = 128; COsrc = 192; o0 = 0;   WCO = 192; break;
        case 7:  src = wx_b1;   off = OFF_XB1;  CIN = 128; COsrc = 192; o0 = 0;   WCO = 192; break;
        case 8:  src = wh_f1;   off = OFF_ZRF1; CIN = 64;  COsrc = 192; o0 = 0;   WCO = 128; break;
        case 9:  src = wh_b1;   off = OFF_ZRB1; CIN = 64;  COsrc = 192; o0 = 0;   WCO = 128; break;
        case 10: src = wh_f1;   off = OFF_HF1;  CIN = 64;  COsrc = 192; o0 = 128; WCO = 64;  break;
        case 11: src = wh_b1;   off = OFF_HB1;  CIN = 64;  COsrc = 192; o0 = 128; WCO = 64;  break;
        default: src = w_conv1; off = OFF_C1;   CIN = 256; COsrc = 32;  o0 = 0;   WCO = 32;  break;
    }
    int n = 9 * (CIN / 2) * WCO;
    int i = blockIdx.x * 256 + threadIdx.x;
    if (i >= n) return;
    int co = i % WCO;
    int r = i / WCO;
    int cp = r % (CIN / 2);
    int tap = r / (CIN / 2);
    float* dst = WT + off;
    dst[(long)i * 2 + 0] = src[((long)tap * CIN + 2 * cp) * COsrc + o0 + co];
    dst[(long)i * 2 + 1] = src[((long)tap * CIN + 2 * cp + 1) * COsrc + o0 + co];
}

__global__ __launch_bounds__(256) void halo_all_k(
    float* __restrict__ Y0, float* __restrict__ Y1,
    float* __restrict__ RH, float* __restrict__ XC)
{
    float* p; int nImg, C;
    switch (blockIdx.y) {
        case 0: p = Y0; nImg = NIMG_; C = 128; break;
        case 1: p = Y1; nImg = NIMG_; C = 128; break;
        case 2: p = RH; nImg = 32;    C = 64;  break;
        default: p = XC; nImg = NIMG_; C = 256; break;
    }
    long i = (long)blockIdx.x * 256 + threadIdx.x;
    long tot = (long)nImg * 132 * C;
    if (i >= tot) return;
    int c = (int)(i % C);
    long r = i / C;
    int hidx = (int)(r % 132);
    long img = r / 132;
    int y, x;
    if (hidx < 34)       { y = 0;  x = hidx; }
    else if (hidx < 68)  { y = 33; x = hidx - 34; }
    else if (hidx < 100) { y = hidx - 68 + 1;  x = 0; }
    else                 { y = hidx - 100 + 1; x = 33; }
    p[((long)img * PP_ + (long)y * 34 + x) * C + c] = 0.0f;
}

__global__ __launch_bounds__(256) void pad_x_k(const float* __restrict__ x,
                                               float* __restrict__ xp)
{
    long i = (long)blockIdx.x * 256 + threadIdx.x;   // 448*1156*24
    if (i >= (long)NIMG_ * PP_ * 24) return;
    int c = (int)(i % 24);
    long r = i / 24;
    int pix = (int)(r % PP_);
    long img = r / PP_;
    int y = pix / 34, xx = pix % 34;
    float v = 0.0f;
    if (y >= 1 && y <= 32 && xx >= 1 && xx <= 32)
        v = x[(((long)img * 32 + y - 1) * 32 + xx - 1) * 24 + c];
    xp[i] = v;
}

__global__ __launch_bounds__(256) void addconcat_k(
    const float* __restrict__ Y0, const float* __restrict__ Y1,
    float* __restrict__ XC)
{
    long i = (long)blockIdx.x * 256 + threadIdx.x;   // 448*1024*64 float4 units
    if (i >= (long)NIMG_ * 1024 * 64) return;
    int cq = (int)(i & 63);
    long r = i >> 6;
    int pix = (int)(r & 1023);
    long img = r >> 10;
    int c = cq * 4;
    int y = pix >> 5, xx = pix & 31;
    long pp = (long)(y + 1) * 34 + xx + 1;
    float4 v;
    if (c < 128) {
        float4 a = *(const float4*)(Y0 + (img * PP_ + pp) * 128 + c);
        float4 bq = *(const float4*)(Y1 + (img * PP_ + pp) * 128 + c);
        v = make_float4(a.x + bq.x, a.y + bq.y, a.z + bq.z, a.w + bq.w);
    } else {
        v = *(const float4*)(Y0 + (img * PP_ + pp) * 128 + c - 128);
    }
    *(float4*)(XC + (img * PP_ + pp) * 256 + c) = v;
}

// ---------------------------------------------------------------------------
// Host
// ---------------------------------------------------------------------------
#define SMEM_COL 87040   // 340*32 ull

static void run_layer(const float* XG_, float* Y, float* Z_, float* RH_,
                      const float* WT, long zrF, long zrB, long hF, long hB)
{
    for (int i = 1; i < T_; i++) {
        conv_gh_zrh_k<<<dim3(4, 1, 128), 256, SMEM_COL>>>(Y, WT + zrF, WT + zrB,
                                                          XG_, Z_, RH_, i, T_ - 1 - i);
        conv_blend_k<<<dim3(4, 1, 64), 256, SMEM_COL>>>(RH_, WT + hF, WT + hB,
                                                        XG_, Z_, Y, i, T_ - 1 - i);
    }
}

extern "C" void kernel_launch(void* const* d_in, const int* in_sizes, int n_in,
                              void* d_out, int out_size)
{
    (void)in_sizes; (void)n_in; (void)out_size;
    const float* x       = (const float*)d_in[0];
    const float* wx_f0   = (const float*)d_in[1];
    const float* wh_f0   = (const float*)d_in[2];
    const float* b_f0    = (const float*)d_in[3];
    const float* wx_b0   = (const float*)d_in[4];
    const float* wh_b0   = (const float*)d_in[5];
    const float* b_b0    = (const float*)d_in[6];
    const float* wx_f1   = (const float*)d_in[7];
    const float* wh_f1   = (const float*)d_in[8];
    const float* b_f1    = (const float*)d_in[9];
    const float* wx_b1   = (const float*)d_in[10];
    const float* wh_b1   = (const float*)d_in[11];
    const float* b_b1    = (const float*)d_in[12];
    const float* w_conv1 = (const float*)d_in[13];
    const float* b_conv1 = (const float*)d_in[14];
    const float* w_out   = (const float*)d_in[15];
    const float* b_out   = (const float*)d_in[16];

    float *Xpad, *XG, *Y0, *Y1, *RH, *Z, *XC, *WT;
    cudaGetSymbolAddress((void**)&Xpad, g_Xpad);
    cudaGetSymbolAddress((void**)&XG, g_XG);
    cudaGetSymbolAddress((void**)&Y0, g_Y0);
    cudaGetSymbolAddress((void**)&Y1, g_Y1);
    cudaGetSymbolAddress((void**)&RH, g_RH);
    cudaGetSymbolAddress((void**)&Z,  g_Z);
    cudaGetSymbolAddress((void**)&XC, g_XC);
    cudaGetSymbolAddress((void**)&WT, g_WT);

    // allow >48KB dynamic smem (idempotent)
    cudaFuncSetAttribute(conv_gates_k<64, 128>,
                         cudaFuncAttributeMaxDynamicSharedMemorySize, 51200);
    cudaFuncSetAttribute(conv1_out_k,
                         cudaFuncAttributeMaxDynamicSharedMemorySize, 102400);
    cudaFuncSetAttribute(conv_gh_zrh_k,
                         cudaFuncAttributeMaxDynamicSharedMemorySize, SMEM_COL);
    cudaFuncSetAttribute(conv_blend_k,
                         cudaFuncAttributeMaxDynamicSharedMemorySize, SMEM_COL);

    // launch 0: all weight transposes
    transpose_all_k<<<dim3(432, 13), 256>>>(wx_f0, wh_f0, wx_b0, wh_b0,
                                            wx_f1, wh_f1, wx_b1, wh_b1,
                                            w_conv1, WT);
    // launch 1: all halo zeroing
    halo_all_k<<<dim3(59136, 4), 256>>>(Y0, Y1, RH, XC);
    // launch 2: input padding
    {
        long n = (long)NIMG_ * PP_ * 24;
        pad_x_k<<<(unsigned)((n + 255) / 256), 256>>>(x, Xpad);
    }

    // launch 3: layer-0 input gates
    conv_gates_k<12, 24><<<dim3(4, 4, 2 * NIMG_ * 3), 256, 9600>>>(
        Xpad, (long)PP_ * 24, WT + OFF_XF0, WT + OFF_XB0, b_f0, b_b0, XG);
    // launch 4: t=0 step   |   launch 5: conv_gh_zrh_k (ncu target)
    zrh0_k<<<8192, 256>>>(XG, Y0);
    run_layer(XG, Y0, Z, RH, WT, OFF_ZRF0, OFF_ZRB0, OFF_HF0, OFF_HB0);

    // layer 1
    conv_gates_k<64, 128><<<dim3(4, 4, 2 * NIMG_ * 3), 256, 51200>>>(
        Y0, (long)PP_ * 128, WT + OFF_XF1, WT + OFF_XB1, b_f1, b_b1, XG);
    zrh0_k<<<8192, 256>>>(XG, Y1);
    run_layer(XG, Y1, Z, RH, WT, OFF_ZRF1, OFF_ZRB1, OFF_HF1, OFF_HB1);

    // xr = Y0+Y1, xc = [xr, Y0]
    {
        long n = (long)NIMG_ * 1024 * 64;
        addconcat_k<<<(unsigned)((n + 255) / 256), 256>>>(Y0, Y1, XC);
    }

    // conv1 + 1x1 + relu
    conv1_out_k<<<dim3(4, 4, NIMG_), 256, 102400>>>(XC, WT + OFF_C1, b_conv1, w_out, b_out,
                                                    (float*)d_out);
}

// round 17
// speedup vs baseline: 1.1352x; 1.1352x over previous
#include <cuda_runtime.h>
#include <cuda_bf16.h>
#include <math.h>

typedef unsigned long long ull;
typedef unsigned int u32;

#define B_ 16
#define T_ 28
#define NIMG_ 448
#define PP_ 1156

// ---------------- device scratch ----------------
__device__ float g_XG[(size_t)2 * NIMG_ * 1024 * 192];
__device__ float g_Y0[(size_t)NIMG_ * PP_ * 128];
__device__ float g_Y1[(size_t)NIMG_ * PP_ * 128];
__device__ float g_RH[(size_t)32 * PP_ * 64];
__device__ float g_Z [(size_t)32 * 1024 * 64];
__device__ float g_WT[1041408];
__device__ float g_H1[(size_t)NIMG_ * 1024 * 32];
// bf16 activation planes (hi/lo split), zero halo
__device__ __nv_bfloat16 g_XHi[(size_t)NIMG_ * PP_ * 32];
__device__ __nv_bfloat16 g_XLo[(size_t)NIMG_ * PP_ * 32];
__device__ __nv_bfloat16 g_YHi[(size_t)NIMG_ * PP_ * 128];
__device__ __nv_bfloat16 g_YLo[(size_t)NIMG_ * PP_ * 128];
__device__ __nv_bfloat16 g_CHi[(size_t)NIMG_ * PP_ * 256];
__device__ __nv_bfloat16 g_CLo[(size_t)NIMG_ * PP_ * 256];
// packed bf16 B chunk tiles: [slice][chunk][n][32k]
__device__ __nv_bfloat16 g_WB[1880064];
#define WB_L0 0
#define WB_L1 331776
#define WB_C1 1658880

// recurrent transposed-weight offsets (floats)
#define OFF_ZRF0  82944
#define OFF_ZRB0  156672
#define OFF_HF0   230400
#define OFF_HB0   267264
#define OFF_ZRF1  746496
#define OFF_ZRB1  820224
#define OFF_HF1   893952
#define OFF_HB1   930816

// ---------------- scalar helpers ----------------
__device__ __forceinline__ void fma2(ull& d, ull a, ull b) {
    asm("fma.rn.f32x2 %0, %1, %2, %0;" : "+l"(d) : "l"(a), "l"(b));
}
__device__ __forceinline__ float red2(ull a) {
    float lo, hi;
    asm("mov.b64 {%0,%1}, %2;" : "=f"(lo), "=f"(hi) : "l"(a));
    return lo + hi;
}
__device__ __forceinline__ float sigm(float x) { return 1.0f / (1.0f + expf(-x)); }

// ---------------- mma helpers (plain sm_80+ features) ----------------
__device__ __forceinline__ u32 smem_u32(const void* p) {
    u32 a;
    asm("{ .reg .u64 t; cvta.to.shared.u64 t, %1; cvt.u32.u64 %0, t; }" : "=r"(a) : "l"(p));
    return a;
}
__device__ __forceinline__ void ldsm4(u32* r, u32 addr) {
    asm volatile("ldmatrix.sync.aligned.m8n8.x4.shared.b16 {%0,%1,%2,%3}, [%4];"
        : "=r"(r[0]), "=r"(r[1]), "=r"(r[2]), "=r"(r[3]) : "r"(addr));
}
__device__ __forceinline__ void mma16816(float* d, const u32* a, u32 b0, u32 b1) {
    asm volatile("mma.sync.aligned.m16n8k16.row.col.f32.bf16.bf16.f32 "
        "{%0,%1,%2,%3}, {%4,%5,%6,%7}, {%8,%9}, {%0,%1,%2,%3};"
        : "+f"(d[0]), "+f"(d[1]), "+f"(d[2]), "+f"(d[3])
        : "r"(a[0]), "r"(a[1]), "r"(a[2]), "r"(a[3]), "r"(b0), "r"(b1));
}
__device__ __forceinline__ void cp16(u32 dst, const void* src, u32 sz) {
    asm volatile("cp.async.ca.shared.global [%0], [%1], 16, %2;"
                 :: "r"(dst), "l"(src), "r"(sz));
}

// ---------------------------------------------------------------------------
// Implicit-GEMM 3x3 conv via mma.sync bf16 (hi/lo split folded into K).
// CTA: M=128 padded pixels x N=NSL couts; 8 warps = 4(M) x 2(N); warp 32 x NSL/2.
// K walk: 9 taps x 3 phases x KC, in 32-k cp.async double-buffered chunks.
// A from zero-halo planes shifted by tap; B from pre-packed chunk tiles.
// ldmatrix.x4 on B returns r0=(n0-7,k0-7) r1=(n8-15,k0-7) r2=(n0-7,k8-15)
// r3=(n8-15,k8-15): mma B operand pairs are {r0,r2} and {r1,r3}.
// ---------------------------------------------------------------------------
template<int KC, int NSL, int GATES>
__global__ __launch_bounds__(256) void mma_conv_k(
    const __nv_bfloat16* __restrict__ AHi, const __nv_bfloat16* __restrict__ ALo,
    const __nv_bfloat16* __restrict__ WB,
    const float* __restrict__ bF, const float* __restrict__ bB,
    float* __restrict__ outp)
{
    extern __shared__ char smem[];
    const int tid = threadIdx.x;
    const int lane = tid & 31, wrp = tid >> 5;
    const int warpM = wrp & 3, warpN = wrp >> 2;
    const int mtile = blockIdx.x, img = blockIdx.y, slice = blockIdx.z;
    constexpr int CPT = 3 * KC / 32;     // chunks per tap
    constexpr int CH  = 9 * CPT;
    constexpr int NN  = NSL / 16;        // n8 frags per warp
    const int mbase = mtile * 128;

    const u32 sA = smem_u32(smem);
    const u32 sB = sA + 20480;
    const __nv_bfloat16* wbS = WB + (long)slice * CH * NSL * 32;

    auto stage = [&](int ch, int buf) {
        int tap = ch / CPT, cip = ch - tap * CPT;
        int ph = cip / (KC / 32);
        int kc = (cip - ph * (KC / 32)) * 32;
        const __nv_bfloat16* plane = (ph == 2) ? ALo : AHi;
        int delta = (tap / 3 - 1) * 34 + (tap % 3) - 1;
        u32 aB = sA + buf * 10240;
#pragma unroll
        for (int i = tid; i < 512; i += 256) {
            int r2 = i >> 2, q = i & 3;
            int p = mbase + r2 + delta;
            bool ok = (p >= 0 && p < PP_);
            const void* src = plane + ((long)img * PP_ + (ok ? p : 0)) * KC + kc + q * 8;
            cp16(aB + r2 * 80 + q * 16, src, ok ? 16u : 0u);
        }
        u32 bBuf = sB + buf * (NSL * 80);
#pragma unroll
        for (int i = tid; i < NSL * 4; i += 256) {
            int n = i >> 2, q = i & 3;
            const void* src = wbS + ((long)ch * NSL + n) * 32 + q * 8;
            cp16(bBuf + n * 80 + q * 16, src, 16u);
        }
        asm volatile("cp.async.commit_group;" ::: "memory");
    };

    float d[2][NN][4];
#pragma unroll
    for (int mt = 0; mt < 2; mt++)
#pragma unroll
        for (int j = 0; j < NN; j++)
#pragma unroll
            for (int c = 0; c < 4; c++) d[mt][j][c] = 0.0f;

    stage(0, 0);
    for (int ch = 0; ch < CH; ch++) {
        if (ch + 1 < CH) {
            stage(ch + 1, (ch + 1) & 1);
            asm volatile("cp.async.wait_group 1;" ::: "memory");
        } else {
            asm volatile("cp.async.wait_group 0;" ::: "memory");
        }
        __syncthreads();
        u32 aB = sA + (ch & 1) * 10240;
        u32 bBuf = sB + (ch & 1) * (NSL * 80);
#pragma unroll
        for (int ks = 0; ks < 2; ks++) {
            u32 a[2][4];
#pragma unroll
            for (int mt = 0; mt < 2; mt++)
                ldsm4(a[mt], aB + (warpM * 32 + mt * 16 + (lane & 15)) * 80
                             + ks * 32 + (lane >> 4) * 16);
            u32 b[NN / 2][4];
#pragma unroll
            for (int ng = 0; ng < NN / 2; ng++)
                ldsm4(b[ng], bBuf + (warpN * (NSL / 2) + ng * 16 + (lane & 15)) * 80
                             + ks * 32 + (lane >> 4) * 16);
#pragma unroll
            for (int mt = 0; mt < 2; mt++)
#pragma unroll
                for (int ng = 0; ng < NN / 2; ng++) {
                    mma16816(d[mt][ng * 2],     a[mt], b[ng][0], b[ng][2]);
                    mma16816(d[mt][ng * 2 + 1], a[mt], b[ng][1], b[ng][3]);
                }
        }
        __syncthreads();
    }

    // ---- epilogue ----
    if (GATES) {
        int dir = slice / 3, sl = slice - dir * 3;
        const float* bias = dir ? bB : bF;
        float* xg = outp + ((long)dir * NIMG_ + img) * 1024 * 192;
#pragma unroll
        for (int mt = 0; mt < 2; mt++) {
            int row0 = mbase + warpM * 32 + mt * 16 + (lane >> 2);
#pragma unroll
            for (int j = 0; j < NN; j++) {
                int cout = sl * 64 + warpN * (NSL / 2) + j * 8 + (lane & 3) * 2;
                float b0 = __ldg(bias + cout), b1 = __ldg(bias + cout + 1);
#pragma unroll
                for (int rr = 0; rr < 2; rr++) {
                    int p = row0 + rr * 8;
                    int py = p / 34, px = p - py * 34;
                    if (p < PP_ && py >= 1 && py <= 32 && px >= 1 && px <= 32) {
                        float2 v = make_float2(d[mt][j][rr * 2] + b0,
                                               d[mt][j][rr * 2 + 1] + b1);
                        *(float2*)(xg + ((long)(py - 1) * 32 + px - 1) * 192 + cout) = v;
                    }
                }
            }
        }
    } else {
#pragma unroll
        for (int mt = 0; mt < 2; mt++) {
            int row0 = mbase + warpM * 32 + mt * 16 + (lane >> 2);
#pragma unroll
            for (int j = 0; j < NN; j++) {
                int cout = warpN * (NSL / 2) + j * 8 + (lane & 3) * 2;
                float b0 = __ldg(bF + cout), b1 = __ldg(bF + cout + 1);
#pragma unroll
                for (int rr = 0; rr < 2; rr++) {
                    int p = row0 + rr * 8;
                    int py = p / 34, px = p - py * 34;
                    if (p < PP_ && py >= 1 && py <= 32 && px >= 1 && px <= 32) {
                        float2 v = make_float2(d[mt][j][rr * 2] + b0,
                                               d[mt][j][rr * 2 + 1] + b1);
                        *(float2*)(outp + ((long)img * 1024
                                   + (py - 1) * 32 + px - 1) * 32 + cout) = v;
                    }
                }
            }
        }
    }
}

// ---------------------------------------------------------------------------
// 1x1 head: out = relu(sum_c H1[c]*wo[c] + bo)  (H1 already has b_conv1 added)
// ---------------------------------------------------------------------------
__global__ __launch_bounds__(256) void head_k(
    const float* __restrict__ H1, const float* __restrict__ wo,
    const float* __restrict__ bo, float* __restrict__ out)
{
    int i = blockIdx.x * 256 + threadIdx.x;   // 448*1024
    const float* h = H1 + (long)i * 32;
    float s = __ldg(bo);
#pragma unroll
    for (int c = 0; c < 32; c++) s += h[c] * __ldg(wo + c);
    out[i] = fmaxf(s, 0.0f);
}

// ---------------------------------------------------------------------------
// prep: x bf16 hi/lo planes (zero halo, 24ch padded to 32)
// ---------------------------------------------------------------------------
__global__ __launch_bounds__(256) void prep_x_k(const float* __restrict__ x)
{
    long i = (long)blockIdx.x * 256 + threadIdx.x;
    if (i >= (long)NIMG_ * PP_ * 32) return;
    int c = (int)(i & 31);
    long r = i >> 5;
    int pp = (int)(r % PP_);
    long img = r / PP_;
    int py = pp / 34, px = pp % 34;
    float v = 0.0f;
    if (c < 24 && py >= 1 && py <= 32 && px >= 1 && px <= 32)
        v = x[(((long)img * 32 + py - 1) * 32 + px - 1) * 24 + c];
    __nv_bfloat16 h = __float2bfloat16(v);
    g_XHi[i] = h;
    g_XLo[i] = __float2bfloat16(v - __bfloat162float(h));
}

// ---------------------------------------------------------------------------
// pack B chunk tiles for all three convs.
// layout: base + ((slice*CH + ch)*NSL + n)*32 + k ;
// ch -> tap = ch/CPT, phase = (ch%CPT)/(KC/32), kc = (ch%CPT)%(KC/32)*32.
// phase 0: Whi, 1: Wlo, 2: Whi  (pairs A=[Ahi,Ahi,Alo]).
// ---------------------------------------------------------------------------
__global__ __launch_bounds__(256) void pack_b_k(
    const float* __restrict__ wx_f0, const float* __restrict__ wx_b0,
    const float* __restrict__ wx_f1, const float* __restrict__ wx_b1,
    const float* __restrict__ w_conv1)
{
    long i = (long)blockIdx.x * 256 + threadIdx.x;
    if (i >= 1880064) return;
    int conv; long sub;
    if (i < WB_L1)      { conv = 0; sub = i; }
    else if (i < WB_C1) { conv = 1; sub = i - WB_L1; }
    else                { conv = 2; sub = i - WB_C1; }
    int KC  = (conv == 0) ? 32 : (conv == 1) ? 128 : 256;
    int NSL = (conv == 2) ? 32 : 64;
    int k = (int)(sub & 31);
    long r = sub >> 5;
    int n = (int)(r % NSL); r /= NSL;
    int CPT = 3 * KC / 32;
    int CH = 9 * CPT;
    int ch = (int)(r % CH);
    int s  = (int)(r / CH);
    int tap = ch / CPT, cip = ch - tap * CPT;
    int ph = cip / (KC / 32);
    int kc = (cip - ph * (KC / 32)) * 32;
    int cin = kc + k;
    float w = 0.0f;
    if (conv == 2) {
        w = w_conv1[((long)tap * 256 + cin) * 32 + n];
    } else {
        int dir = s / 3, sl = s - dir * 3;
        int cout = sl * 64 + n;
        int CinR = (conv == 0) ? 24 : 128;
        const float* src = (conv == 0) ? (dir ? wx_b0 : wx_f0)
                                       : (dir ? wx_b1 : wx_f1);
        if (cin < CinR) w = src[((long)tap * CinR + cin) * 192 + cout];
    }
    __nv_bfloat16 hi = __float2bfloat16(w);
    g_WB[i] = (ph == 1) ? __float2bfloat16(w - __bfloat162float(hi)) : hi;
}

__global__ __launch_bounds__(256) void conv_y_k(const float* __restrict__ Y)
{
    long i = (long)blockIdx.x * 256 + threadIdx.x;
    if (i >= (long)NIMG_ * PP_ * 128) return;
    float v = Y[i];
    __nv_bfloat16 h = __float2bfloat16(v);
    g_YHi[i] = h;
    g_YLo[i] = __float2bfloat16(v - __bfloat162float(h));
}

__global__ __launch_bounds__(256) void addconcat_bf_k(
    const float* __restrict__ Y0, const float* __restrict__ Y1)
{
    long i = (long)blockIdx.x * 256 + threadIdx.x;
    if (i >= (long)NIMG_ * PP_ * 256) return;
    int c = (int)(i & 255);
    long r = i >> 8;
    float v;
    if (c < 128) v = Y0[r * 128 + c] + Y1[r * 128 + c];
    else         v = Y0[r * 128 + c - 128];
    __nv_bfloat16 h = __float2bfloat16(v);
    g_CHi[i] = h;
    g_CLo[i] = __float2bfloat16(v - __bfloat162float(h));
}

// ---------------------------------------------------------------------------
// Recurrent path (round-4/5 proven): full-column smem tiles + packed f32x2.
// ---------------------------------------------------------------------------
template<int CINH, int CSTRIDE>
__device__ __forceinline__ void stage_col(const float* __restrict__ gBase, ull* s)
{
    constexpr int TOT = 340 * CINH;
#pragma unroll 4
    for (int i = threadIdx.x; i < TOT; i += 256) {
        int r = i / (10 * CINH);
        int rem = i - r * (10 * CINH);
        int c = rem / CINH;
        int cp = rem - c * CINH;
        s[i] = *(const ull*)(gBase + (long)(r * 34 + c) * CSTRIDE + 2 * cp);
    }
}

template<int CINH, int WCO>
__device__ __forceinline__ void conv_core4(
    const ull* sT, int warp, const float* __restrict__ wt, int coutIdx, ull acc[4][8])
{
#pragma unroll
    for (int o = 0; o < 4; o++)
#pragma unroll
        for (int p = 0; p < 8; p++) acc[o][p] = 0ull;
    const ull* sW = sT + (4 * warp) * 10 * CINH;
    const float* wP = wt + coutIdx * 2;
#pragma unroll 1
    for (int cp = 0; cp < CINH; cp++) {
        ull w[9];
#pragma unroll
        for (int t = 0; t < 9; t++) w[t] = *(const ull*)(wP + (long)t * CINH * WCO * 2);
#pragma unroll
        for (int r = 0; r < 6; r++) {
            ull v[10];
#pragma unroll
            for (int q = 0; q < 10; q++) v[q] = sW[(r * 10 + q) * CINH + cp];
#pragma unroll
            for (int o = 0; o < 4; o++) {
                if (o <= r && r <= o + 2) {
                    int ky = r - o;
#pragma unroll
                    for (int kx = 0; kx < 3; kx++)
#pragma unroll
                        for (int p = 0; p < 8; p++)
                            fma2(acc[o][p], v[p + kx], w[ky * 3 + kx]);
                }
            }
        }
        wP += WCO * 2;
    }
}

__global__ __launch_bounds__(256, 2) void conv_gh_zrh_k(
    const float* __restrict__ Y,
    const float* __restrict__ wtF, const float* __restrict__ wtB,
    const float* __restrict__ XG, float* __restrict__ Z, float* __restrict__ RH,
    int tf, int tb)
{
    extern __shared__ ull sdyn[];
    int z = blockIdx.z;
    int dir = z >> 6, b = (z >> 2) & 15, cg = z & 3;
    int lane = threadIdx.x & 31, warp = threadIdx.x >> 5;
    int bx = blockIdx.x;
    int t = dir ? tb : tf;
    int tprev = dir ? tb + 1 : tf - 1;

    const float* hbase = Y + (long)(b * T_ + tprev) * PP_ * 128 + (dir ? 64 : 0);
    stage_col<32, 128>(hbase + (long)(bx * 8) * 128, sdyn);
    __syncthreads();

    ull acc[4][8];
    conv_core4<32, 128>(sdyn, warp, dir ? wtB : wtF, cg * 32 + lane, acc);

    int zr = cg >> 1;
    int c = (cg & 1) * 32 + lane;
    const float* xg = XG + ((long)dir * NIMG_ + b * T_ + t) * 1024 * 192;
    if (zr == 0) {
        float* zp = Z + (long)(dir * 16 + b) * 1024 * 64;
#pragma unroll
        for (int o = 0; o < 4; o++) {
            int py = 4 * warp + o;
#pragma unroll
            for (int p = 0; p < 8; p++) {
                int pix = py * 32 + bx * 8 + p;
                zp[(long)pix * 64 + c] = sigm(xg[(long)pix * 192 + c] + red2(acc[o][p]));
            }
        }
    } else {
        float* rh = RH + (long)(dir * 16 + b) * PP_ * 64;
#pragma unroll
        for (int o = 0; o < 4; o++) {
            int y = 4 * warp + 1 + o;
#pragma unroll
            for (int p = 0; p < 8; p++) {
                int x = bx * 8 + 1 + p;
                int pix = (y - 1) * 32 + (x - 1);
                float r = sigm(xg[(long)pix * 192 + 64 + c] + red2(acc[o][p]));
                float h = hbase[((long)y * 34 + x) * 128 + c];
                rh[((long)y * 34 + x) * 64 + c] = r * h;
            }
        }
    }
}

__global__ __launch_bounds__(256, 2) void conv_blend_k(
    const float* __restrict__ RH,
    const float* __restrict__ wtF, const float* __restrict__ wtB,
    const float* __restrict__ XG, const float* __restrict__ Z,
    float* __restrict__ Y, int tf, int tb)
{
    extern __shared__ ull sdyn[];
    int z = blockIdx.z;
    int dir = z >> 5, b = (z >> 1) & 15, cg = z & 1;
    int lane = threadIdx.x & 31, warp = threadIdx.x >> 5;
    int bx = blockIdx.x;
    int t = dir ? tb : tf;
    int tprev = dir ? tb + 1 : tf - 1;

    const float* in = RH + (long)(dir * 16 + b) * PP_ * 64;
    stage_col<32, 64>(in + (long)(bx * 8) * 64, sdyn);
    __syncthreads();

    ull acc[4][8];
    conv_core4<32, 64>(sdyn, warp, dir ? wtB : wtF, cg * 32 + lane, acc);

    int c = cg * 32 + lane;
    const float* xg = XG + ((long)dir * NIMG_ + b * T_ + t) * 1024 * 192;
    const float* zp = Z + (long)(dir * 16 + b) * 1024 * 64;
    const float* hprev = Y + (long)(b * T_ + tprev) * PP_ * 128 + (dir ? 64 : 0);
    float* yout = Y + (long)(b * T_ + t) * PP_ * 128 + (dir ? 64 : 0);
#pragma unroll
    for (int o = 0; o < 4; o++) {
        int y = 4 * warp + 1 + o;
#pragma unroll
        for (int p = 0; p < 8; p++) {
            int x = bx * 8 + 1 + p;
            int pix = (y - 1) * 32 + (x - 1);
            float cand = tanhf(xg[(long)pix * 192 + 128 + c] + red2(acc[o][p]));
            float zv = zp[(long)pix * 64 + c];
            float hv = hprev[((long)y * 34 + x) * 128 + c];
            yout[((long)y * 34 + x) * 128 + c] = zv * hv + (1.0f - zv) * cand;
        }
    }
}

__global__ __launch_bounds__(256) void zrh0_k(const float* __restrict__ XG,
                                              float* __restrict__ Y)
{
    int i = blockIdx.x * 256 + threadIdx.x;
    int c = i & 63;
    int t1 = i >> 6;
    int pix = t1 & 1023;
    int t2 = t1 >> 10;
    int b = t2 & 15, dir = t2 >> 4;
    int t = dir ? T_ - 1 : 0;
    const float* xg = XG + (((long)dir * NIMG_ + b * T_ + t) * 1024 + pix) * 192;
    float zv = sigm(xg[c]);
    float yv = (1.0f - zv) * tanhf(xg[128 + c]);
    int yy = pix >> 5, xx = pix & 31;
    Y[((long)(b * T_ + t) * PP_ + (long)(yy + 1) * 34 + xx + 1) * 128 + dir * 64 + c] = yv;
}

__global__ __launch_bounds__(256) void transpose_all_k(
    const float* __restrict__ wh_f0, const float* __restrict__ wh_b0,
    const float* __restrict__ wh_f1, const float* __restrict__ wh_b1,
    float* __restrict__ WT)
{
    const float* src; long off; int o0, WCO;
    switch (blockIdx.y) {
        case 0:  src = wh_f0; off = OFF_ZRF0; o0 = 0;   WCO = 128; break;
        case 1:  src = wh_b0; off = OFF_ZRB0; o0 = 0;   WCO = 128; break;
        case 2:  src = wh_f0; off = OFF_HF0;  o0 = 128; WCO = 64;  break;
        case 3:  src = wh_b0; off = OFF_HB0;  o0 = 128; WCO = 64;  break;
        case 4:  src = wh_f1; off = OFF_ZRF1; o0 = 0;   WCO = 128; break;
        case 5:  src = wh_b1; off = OFF_ZRB1; o0 = 0;   WCO = 128; break;
        case 6:  src = wh_f1; off = OFF_HF1;  o0 = 128; WCO = 64;  break;
        default: src = wh_b1; off = OFF_HB1;  o0 = 128; WCO = 64;  break;
    }
    int n = 9 * 32 * WCO;
    int i = blockIdx.x * 256 + threadIdx.x;
    if (i >= n) return;
    int co = i % WCO;
    int r = i / WCO;
    int cp = r % 32;
    int tap = r / 32;
    float* dst = WT + off;
    dst[(long)i * 2 + 0] = src[((long)tap * 64 + 2 * cp) * 192 + o0 + co];
    dst[(long)i * 2 + 1] = src[((long)tap * 64 + 2 * cp + 1) * 192 + o0 + co];
}

__global__ __launch_bounds__(256) void halo_one_k(float* __restrict__ p, int nImg, int C)
{
    long i = (long)blockIdx.x * 256 + threadIdx.x;
    long tot = (long)nImg * 132 * C;
    if (i >= tot) return;
    int c = (int)(i % C);
    long r = i / C;
    int hidx = (int)(r % 132);
    long img = r / 132;
    int y, x;
    if (hidx < 34)       { y = 0;  x = hidx; }
    else if (hidx < 68)  { y = 33; x = hidx - 34; }
    else if (hidx < 100) { y = hidx - 68 + 1;  x = 0; }
    else                 { y = hidx - 100 + 1; x = 33; }
    p[((long)img * PP_ + (long)y * 34 + x) * C + c] = 0.0f;
}

// ---------------------------------------------------------------------------
// Host
// ---------------------------------------------------------------------------
#define SMEM_COL 87040

static void run_layer(const float* XG_, float* Y, float* Z_, float* RH_,
                      const float* WT, long zrF, long zrB, long hF, long hB)
{
    for (int i = 1; i < T_; i++) {
        conv_gh_zrh_k<<<dim3(4, 1, 128), 256, SMEM_COL>>>(Y, WT + zrF, WT + zrB,
                                                          XG_, Z_, RH_, i, T_ - 1 - i);
        conv_blend_k<<<dim3(4, 1, 64), 256, SMEM_COL>>>(RH_, WT + hF, WT + hB,
                                                        XG_, Z_, Y, i, T_ - 1 - i);
    }
}

extern "C" void kernel_launch(void* const* d_in, const int* in_sizes, int n_in,
                              void* d_out, int out_size)
{
    (void)in_sizes; (void)n_in; (void)out_size;
    const float* x       = (const float*)d_in[0];
    const float* wx_f0   = (const float*)d_in[1];
    const float* wh_f0   = (const float*)d_in[2];
    const float* b_f0    = (const float*)d_in[3];
    const float* wx_b0   = (const float*)d_in[4];
    const float* wh_b0   = (const float*)d_in[5];
    const float* b_b0    = (const float*)d_in[6];
    const float* wx_f1   = (const float*)d_in[7];
    const float* wh_f1   = (const float*)d_in[8];
    const float* b_f1    = (const float*)d_in[9];
    const float* wx_b1   = (const float*)d_in[10];
    const float* wh_b1   = (const float*)d_in[11];
    const float* b_b1    = (const float*)d_in[12];
    const float* w_conv1 = (const float*)d_in[13];
    const float* b_conv1 = (const float*)d_in[14];
    const float* w_out   = (const float*)d_in[15];
    const float* b_out   = (const float*)d_in[16];

    float *XG, *Y0, *Y1, *RH, *Z, *WT, *H1;
    __nv_bfloat16 *XHi, *XLo, *YHi, *YLo, *CHi, *CLo, *WB;
    cudaGetSymbolAddress((void**)&XG, g_XG);
    cudaGetSymbolAddress((void**)&Y0, g_Y0);
    cudaGetSymbolAddress((void**)&Y1, g_Y1);
    cudaGetSymbolAddress((void**)&RH, g_RH);
    cudaGetSymbolAddress((void**)&Z,  g_Z);
    cudaGetSymbolAddress((void**)&WT, g_WT);
    cudaGetSymbolAddress((void**)&H1, g_H1);
    cudaGetSymbolAddress((void**)&XHi, g_XHi);
    cudaGetSymbolAddress((void**)&XLo, g_XLo);
    cudaGetSymbolAddress((void**)&YHi, g_YHi);
    cudaGetSymbolAddress((void**)&YLo, g_YLo);
    cudaGetSymbolAddress((void**)&CHi, g_CHi);
    cudaGetSymbolAddress((void**)&CLo, g_CLo);
    cudaGetSymbolAddress((void**)&WB, g_WB);

    cudaFuncSetAttribute(conv_gh_zrh_k,
                         cudaFuncAttributeMaxDynamicSharedMemorySize, SMEM_COL);
    cudaFuncSetAttribute(conv_blend_k,
                         cudaFuncAttributeMaxDynamicSharedMemorySize, SMEM_COL);

    // 0: x planes, 1: B pack, 2-4: halo zero
    {
        long n = (long)NIMG_ * PP_ * 32;
        prep_x_k<<<(unsigned)((n + 255) / 256), 256>>>(x);
    }
    pack_b_k<<<7344, 256>>>(wx_f0, wx_b0, wx_f1, wx_b1, w_conv1);
    halo_one_k<<<(NIMG_ * 132 * 128 + 255) / 256, 256>>>(Y0, NIMG_, 128);
    halo_one_k<<<(NIMG_ * 132 * 128 + 255) / 256, 256>>>(Y1, NIMG_, 128);
    halo_one_k<<<(32 * 132 * 64 + 255) / 256, 256>>>(RH, 32, 64);

    // 5: layer-0 gates via mma.sync (ncu target)
    mma_conv_k<32, 64, 1><<<dim3(10, NIMG_, 6), 256, 30720>>>(
        XHi, XLo, WB + WB_L0, b_f0, b_b0, XG);
    transpose_all_k<<<dim3(144, 8), 256>>>(wh_f0, wh_b0, wh_f1, wh_b1, WT);
    zrh0_k<<<8192, 256>>>(XG, Y0);
    run_layer(XG, Y0, Z, RH, WT, OFF_ZRF0, OFF_ZRB0, OFF_HF0, OFF_HB0);

    // layer 1
    {
        long n = (long)NIMG_ * PP_ * 128;
        conv_y_k<<<(unsigned)((n + 255) / 256), 256>>>(Y0);
    }
    mma_conv_k<128, 64, 1><<<dim3(10, NIMG_, 6), 256, 30720>>>(
        YHi, YLo, WB + WB_L1, b_f1, b_b1, XG);
    zrh0_k<<<8192, 256>>>(XG, Y1);
    run_layer(XG, Y1, Z, RH, WT, OFF_ZRF1, OFF_ZRB1, OFF_HF1, OFF_HB1);

    // concat planes + conv1 + head
    {
        long n = (long)NIMG_ * PP_ * 256;
        addconcat_bf_k<<<(unsigned)((n + 255) / 256), 256>>>(Y0, Y1);
    }
    mma_conv_k<256, 32, 0><<<dim3(10, NIMG_, 1), 256, 25600>>>(
        CHi, CLo, WB + WB_C1, b_conv1, b_conv1, H1);
    head_k<<<1792, 256>>>(H1, w_out, b_out, (float*)d_out);
}